// round 3
// baseline (speedup 1.0000x reference)
#include <cuda_runtime.h>
#include <math.h>

// ---------------- problem constants ----------------
#define Bb   2
#define Ss   1024
#define Dd   2048
#define Hh   16
#define DHh  128
#define Ee   8
#define HIDh 4096
#define Tt   (Bb * Ss)       // 2048 tokens
#define NPAIR (Tt * 2)       // 4096 (token, expert) pairs, always exactly this

// ---------------- device scratch (no allocations allowed) ----------------
__device__ float g_xn1[Tt * Dd];
__device__ float g_q  [Tt * Dd];
__device__ float g_k  [Tt * Dd];
__device__ float g_v  [Tt * Dd];
__device__ float g_att[Tt * Dd];
__device__ float g_x2 [Tt * Dd];
__device__ float g_xn2[Tt * Dd];
__device__ int   g_tid2[NPAIR];     // per (token,k) expert id
__device__ float g_twt [NPAIR];     // per (token,k) routing weight
__device__ int   g_cnt[Ee];
__device__ int   g_off[Ee];
__device__ int   g_tok[NPAIR];      // expert-grouped token ids
__device__ int   g_prow[NPAIR];     // (token,k) -> row in grouped buffers
__device__ float g_gb[(size_t)NPAIR * HIDh];   // gate -> h (in place)
__device__ float g_ub[(size_t)NPAIR * HIDh];   // up
__device__ float g_eo[(size_t)NPAIR * Dd];     // expert outputs

// ---------------- rmsnorm ----------------
__global__ void rmsnorm_kernel(const float* __restrict__ x,
                               const float* __restrict__ w,
                               float* __restrict__ out) {
    int t = blockIdx.x;
    const float* xr = x + (size_t)t * Dd;
    float ss = 0.f;
    for (int i = threadIdx.x; i < Dd; i += 256) { float vv = xr[i]; ss += vv * vv; }
    __shared__ float red[8];
    #pragma unroll
    for (int o = 16; o; o >>= 1) ss += __shfl_xor_sync(0xffffffffu, ss, o);
    if ((threadIdx.x & 31) == 0) red[threadIdx.x >> 5] = ss;
    __syncthreads();
    if (threadIdx.x < 8) {
        float v = red[threadIdx.x];
        #pragma unroll
        for (int o = 4; o; o >>= 1) v += __shfl_xor_sync(0xffu, v, o);
        if (threadIdx.x == 0) red[0] = v;
    }
    __syncthreads();
    float inv = 1.f / sqrtf(red[0] / (float)Dd + 1e-8f);
    float* orow = out + (size_t)t * Dd;
    for (int i = threadIdx.x; i < Dd; i += 256) orow[i] = xr[i] * inv * w[i];
}

// ---------------- generic sgemm: C[M,N] = A[M,K] @ B[N,K]^T (+bias)(+resid) ----------------
#define BM 128
#define BN 128
#define BK 8

__global__ __launch_bounds__(256, 2)
void sgemm_kernel(const float* __restrict__ A, const float* __restrict__ B,
                  float* __restrict__ C, const float* __restrict__ bias,
                  const float* __restrict__ resid, int N, int K) {
    __shared__ float As[BK][BM];
    __shared__ float Bs[BK][BN];
    const int tid = threadIdx.x;
    const int bm = blockIdx.y * BM;
    const int bn = blockIdx.x * BN;
    const int ty = tid >> 4;          // 0..15
    const int tx = tid & 15;          // 0..15
    const int lr = tid >> 1;          // 0..127
    const int lc = (tid & 1) * 4;     // 0 or 4

    const float* Ap = A + (size_t)(bm + lr) * K + lc;
    const float* Bp = B + (size_t)(bn + lr) * K + lc;

    float acc[8][8];
    #pragma unroll
    for (int i = 0; i < 8; i++)
        #pragma unroll
        for (int j = 0; j < 8; j++) acc[i][j] = 0.f;

    for (int k0 = 0; k0 < K; k0 += BK) {
        float4 a4 = *reinterpret_cast<const float4*>(Ap + k0);
        float4 b4 = *reinterpret_cast<const float4*>(Bp + k0);
        As[lc + 0][lr] = a4.x; As[lc + 1][lr] = a4.y; As[lc + 2][lr] = a4.z; As[lc + 3][lr] = a4.w;
        Bs[lc + 0][lr] = b4.x; Bs[lc + 1][lr] = b4.y; Bs[lc + 2][lr] = b4.z; Bs[lc + 3][lr] = b4.w;
        __syncthreads();
        #pragma unroll
        for (int k = 0; k < BK; k++) {
            float ra[8], rb[8];
            *(float4*)(ra)     = *(const float4*)&As[k][ty * 8];
            *(float4*)(ra + 4) = *(const float4*)&As[k][ty * 8 + 4];
            *(float4*)(rb)     = *(const float4*)&Bs[k][tx * 8];
            *(float4*)(rb + 4) = *(const float4*)&Bs[k][tx * 8 + 4];
            #pragma unroll
            for (int i = 0; i < 8; i++)
                #pragma unroll
                for (int j = 0; j < 8; j++)
                    acc[i][j] = fmaf(ra[i], rb[j], acc[i][j]);
        }
        __syncthreads();
    }
    #pragma unroll
    for (int i = 0; i < 8; i++) {
        int row = bm + ty * 8 + i;
        float* crow = C + (size_t)row * N + bn + tx * 8;
        #pragma unroll
        for (int j = 0; j < 8; j += 4) {
            float4 v;
            v.x = acc[i][j + 0]; v.y = acc[i][j + 1]; v.z = acc[i][j + 2]; v.w = acc[i][j + 3];
            if (bias) {
                int c = bn + tx * 8 + j;
                v.x += bias[c]; v.y += bias[c + 1]; v.z += bias[c + 2]; v.w += bias[c + 3];
            }
            if (resid) {
                float4 r = *(const float4*)(resid + (size_t)row * N + bn + tx * 8 + j);
                v.x += r.x; v.y += r.y; v.z += r.z; v.w += r.w;
            }
            *(float4*)(crow + j) = v;
        }
    }
}

// ---------------- MoE grouped gemm (per-expert segments, optional A gather) ----------------
template <bool GATHER>
__global__ __launch_bounds__(256, 2)
void moe_gemm_kernel(const float* __restrict__ Abase, const float* __restrict__ Bbase,
                     float* __restrict__ Cbase, int N, int K) {
    int e = blockIdx.z;
    int cnt = g_cnt[e];
    int bm = blockIdx.y * BM;
    if (bm >= cnt) return;
    int seg = g_off[e];
    int bn = blockIdx.x * BN;

    __shared__ float As[BK][BM];
    __shared__ float Bs[BK][BN];
    const int tid = threadIdx.x;
    const int ty = tid >> 4;
    const int tx = tid & 15;
    const int lr = tid >> 1;
    const int lc = (tid & 1) * 4;

    int gr = bm + lr;
    if (gr >= cnt) gr = cnt - 1;  // clamp (compute garbage, never stored)
    const float* Ap;
    if (GATHER) Ap = Abase + (size_t)g_tok[seg + gr] * K + lc;
    else        Ap = Abase + (size_t)(seg + gr) * K + lc;
    const float* Bp = Bbase + (size_t)e * N * K + (size_t)(bn + lr) * K + lc;

    float acc[8][8];
    #pragma unroll
    for (int i = 0; i < 8; i++)
        #pragma unroll
        for (int j = 0; j < 8; j++) acc[i][j] = 0.f;

    for (int k0 = 0; k0 < K; k0 += BK) {
        float4 a4 = *reinterpret_cast<const float4*>(Ap + k0);
        float4 b4 = *reinterpret_cast<const float4*>(Bp + k0);
        As[lc + 0][lr] = a4.x; As[lc + 1][lr] = a4.y; As[lc + 2][lr] = a4.z; As[lc + 3][lr] = a4.w;
        Bs[lc + 0][lr] = b4.x; Bs[lc + 1][lr] = b4.y; Bs[lc + 2][lr] = b4.z; Bs[lc + 3][lr] = b4.w;
        __syncthreads();
        #pragma unroll
        for (int k = 0; k < BK; k++) {
            float ra[8], rb[8];
            *(float4*)(ra)     = *(const float4*)&As[k][ty * 8];
            *(float4*)(ra + 4) = *(const float4*)&As[k][ty * 8 + 4];
            *(float4*)(rb)     = *(const float4*)&Bs[k][tx * 8];
            *(float4*)(rb + 4) = *(const float4*)&Bs[k][tx * 8 + 4];
            #pragma unroll
            for (int i = 0; i < 8; i++)
                #pragma unroll
                for (int j = 0; j < 8; j++)
                    acc[i][j] = fmaf(ra[i], rb[j], acc[i][j]);
        }
        __syncthreads();
    }
    #pragma unroll
    for (int i = 0; i < 8; i++) {
        int lrow = bm + ty * 8 + i;
        if (lrow >= cnt) continue;
        float* crow = Cbase + (size_t)(seg + lrow) * N + bn + tx * 8;
        #pragma unroll
        for (int j = 0; j < 8; j += 4) {
            float4 v;
            v.x = acc[i][j + 0]; v.y = acc[i][j + 1]; v.z = acc[i][j + 2]; v.w = acc[i][j + 3];
            *(float4*)(crow + j) = v;
        }
    }
}

// ---------------- RoPE (angle depends on HEAD index, per reference) ----------------
__global__ void rope_kernel(float* __restrict__ q) {
    int gid = blockIdx.x * 256 + threadIdx.x;   // over T * H * 64 pairs
    int t = gid >> 10;
    int r = gid & 1023;
    int h = r >> 6;
    int p = r & 63;
    // inv_freq = 10000^(-p/64); angle = h * inv_freq
    float ang = (float)h * expf(-(float)p * (9.210340371976184f / 64.f));
    float c = cosf(ang), s = sinf(ang);
    float* base = q + (size_t)t * Dd + h * DHh + 2 * p;
    float x1 = base[0], x2 = base[1];
    base[0] = x1 * c - x2 * s;
    base[1] = x1 * s + x2 * c;
}

// ---------------- flash-style causal attention ----------------
#define KT 32
__global__ void attn_kernel(const float* __restrict__ Q, const float* __restrict__ Kx,
                            const float* __restrict__ V, float* __restrict__ O) {
    __shared__ float Ks[KT][DHh];
    __shared__ float Vs[KT][DHh];
    int b = blockIdx.z, h = blockIdx.y, qg = blockIdx.x;
    int warp = threadIdx.x >> 5, lane = threadIdx.x & 31;
    int sq = qg * 8 + warp;
    int tq = b * Ss + sq;
    const float* qrow = Q + (size_t)tq * Dd + h * DHh;
    float qr[4];
    #pragma unroll
    for (int i = 0; i < 4; i++) qr[i] = qrow[lane + 32 * i];
    float m = -INFINITY, l = 0.f, o[4] = {0.f, 0.f, 0.f, 0.f};

    int ntiles = (qg * 8 + 8 + KT - 1) / KT;
    for (int kt = 0; kt < ntiles; kt++) {
        for (int idx = threadIdx.x; idx < KT * DHh; idx += 256) {
            int rr = idx >> 7, cc = idx & 127;
            size_t g = ((size_t)(b * Ss + kt * KT + rr)) * Dd + h * DHh + cc;
            Ks[rr][cc] = Kx[g];
            Vs[rr][cc] = V[g];
        }
        __syncthreads();
        int kmax = sq - kt * KT + 1;
        if (kmax > KT) kmax = KT;
        for (int j = 0; j < kmax; j++) {
            float p = qr[0] * Ks[j][lane] + qr[1] * Ks[j][lane + 32] +
                      qr[2] * Ks[j][lane + 64] + qr[3] * Ks[j][lane + 96];
            #pragma unroll
            for (int ofs = 16; ofs; ofs >>= 1) p += __shfl_xor_sync(0xffffffffu, p, ofs);
            p *= 0.08838834764831845f;  // 1/sqrt(128)
            float mnew = fmaxf(m, p);
            float corr = __expf(m - mnew);
            float w = __expf(p - mnew);
            l = l * corr + w;
            #pragma unroll
            for (int i = 0; i < 4; i++) o[i] = o[i] * corr + w * Vs[j][lane + 32 * i];
            m = mnew;
        }
        __syncthreads();
    }
    float invl = 1.f / l;
    float* orow = O + (size_t)tq * Dd + h * DHh;
    #pragma unroll
    for (int i = 0; i < 4; i++) orow[lane + 32 * i] = o[i] * invl;
}

// ---------------- router: logits, top-2, softmax weights ----------------
__global__ void router_kernel(const float* __restrict__ xn, const float* __restrict__ wr,
                              const float* __restrict__ br) {
    int t = blockIdx.x;
    int warp = threadIdx.x >> 5, lane = threadIdx.x & 31;
    const float* xr = xn + (size_t)t * Dd;
    const float* w = wr + (size_t)warp * Dd;
    float s = 0.f;
    for (int i = lane; i < Dd; i += 32) s += xr[i] * w[i];
    #pragma unroll
    for (int o = 16; o; o >>= 1) s += __shfl_xor_sync(0xffffffffu, s, o);
    __shared__ float lg[Ee];
    if (lane == 0) lg[warp] = s + br[warp];
    __syncthreads();
    if (threadIdx.x == 0) {
        int i0 = 0; float v0 = lg[0];
        for (int e = 1; e < Ee; e++) if (lg[e] > v0) { v0 = lg[e]; i0 = e; }
        int i1 = -1; float v1 = -INFINITY;
        for (int e = 0; e < Ee; e++) if (e != i0 && lg[e] > v1) { v1 = lg[e]; i1 = e; }
        float e1 = expf(v1 - v0);
        float w0 = 1.f / (1.f + e1);
        g_tid2[t * 2] = i0; g_tid2[t * 2 + 1] = i1;
        g_twt[t * 2] = w0;  g_twt[t * 2 + 1] = e1 * w0;
    }
}

// ---------------- single-block expert grouping ----------------
__global__ void build_lists_kernel() {
    __shared__ int cnt[Ee], run[Ee];
    int tid = threadIdx.x;
    if (tid < Ee) cnt[tid] = 0;
    __syncthreads();
    for (int i = tid; i < NPAIR; i += 256) atomicAdd(&cnt[g_tid2[i]], 1);
    __syncthreads();
    if (tid == 0) {
        int acc = 0;
        for (int e = 0; e < Ee; e++) { g_cnt[e] = cnt[e]; g_off[e] = acc; run[e] = acc; acc += cnt[e]; }
    }
    __syncthreads();
    for (int i = tid; i < NPAIR; i += 256) {
        int e = g_tid2[i];
        int pos = atomicAdd(&run[e], 1);
        g_tok[pos] = i >> 1;
        g_prow[i] = pos;
    }
}

// ---------------- h = silu(g) * u (in place into g_gb) ----------------
__global__ void silu_kernel() {
    size_t i = ((size_t)blockIdx.x * 256 + threadIdx.x) * 4;
    float4 g = *(float4*)(g_gb + i);
    float4 u = *(float4*)(g_ub + i);
    g.x = g.x / (1.f + expf(-g.x)) * u.x;
    g.y = g.y / (1.f + expf(-g.y)) * u.y;
    g.z = g.z / (1.f + expf(-g.z)) * u.z;
    g.w = g.w / (1.f + expf(-g.w)) * u.w;
    *(float4*)(g_gb + i) = g;
}

// ---------------- final combine: out = x2 + w0*eo0 + w1*eo1 ----------------
__global__ void combine_kernel(float* __restrict__ out) {
    int t = blockIdx.x;
    int r0 = g_prow[t * 2], r1 = g_prow[t * 2 + 1];
    float w0 = g_twt[t * 2], w1 = g_twt[t * 2 + 1];
    const float* e0 = g_eo + (size_t)r0 * Dd;
    const float* e1 = g_eo + (size_t)r1 * Dd;
    const float* xr = g_x2 + (size_t)t * Dd;
    float* orow = out + (size_t)t * Dd;
    for (int i = threadIdx.x; i < Dd; i += 256)
        orow[i] = xr[i] + w0 * e0[i] + w1 * e1[i];
}

// ---------------- host launcher ----------------
extern "C" void kernel_launch(void* const* d_in, const int* in_sizes, int n_in,
                              void* d_out, int out_size) {
    const float* x   = (const float*)d_in[0];
    const float* wq  = (const float*)d_in[1];
    const float* bq  = (const float*)d_in[2];
    const float* wk  = (const float*)d_in[3];
    const float* bk  = (const float*)d_in[4];
    const float* wv  = (const float*)d_in[5];
    const float* bv  = (const float*)d_in[6];
    const float* wo  = (const float*)d_in[7];
    const float* bo  = (const float*)d_in[8];
    const float* wr  = (const float*)d_in[9];
    const float* br  = (const float*)d_in[10];
    const float* wg  = (const float*)d_in[11];
    const float* wu  = (const float*)d_in[12];
    const float* wd  = (const float*)d_in[13];
    const float* r1w = (const float*)d_in[14];
    const float* r2w = (const float*)d_in[15];
    float* out = (float*)d_out;

    float *xn1, *q, *k, *v, *att, *x2, *xn2, *gb, *ub, *eo;
    cudaGetSymbolAddress((void**)&xn1, g_xn1);
    cudaGetSymbolAddress((void**)&q,   g_q);
    cudaGetSymbolAddress((void**)&k,   g_k);
    cudaGetSymbolAddress((void**)&v,   g_v);
    cudaGetSymbolAddress((void**)&att, g_att);
    cudaGetSymbolAddress((void**)&x2,  g_x2);
    cudaGetSymbolAddress((void**)&xn2, g_xn2);
    cudaGetSymbolAddress((void**)&gb,  g_gb);
    cudaGetSymbolAddress((void**)&ub,  g_ub);
    cudaGetSymbolAddress((void**)&eo,  g_eo);

    // 1) rmsnorm1
    rmsnorm_kernel<<<Tt, 256>>>(x, r1w, xn1);
    // 2) QKV projections
    sgemm_kernel<<<dim3(Dd / BN, Tt / BM), 256>>>(xn1, wq, q, bq, nullptr, Dd, Dd);
    sgemm_kernel<<<dim3(Dd / BN, Tt / BM), 256>>>(xn1, wk, k, bk, nullptr, Dd, Dd);
    sgemm_kernel<<<dim3(Dd / BN, Tt / BM), 256>>>(xn1, wv, v, bv, nullptr, Dd, Dd);
    // 3) RoPE on q, k
    rope_kernel<<<(Tt * Hh * 64) / 256, 256>>>(q);
    rope_kernel<<<(Tt * Hh * 64) / 256, 256>>>(k);
    // 4) causal attention
    attn_kernel<<<dim3(Ss / 8, Hh, Bb), 256>>>(q, k, v, att);
    // 5) output projection + residual
    sgemm_kernel<<<dim3(Dd / BN, Tt / BM), 256>>>(att, wo, x2, bo, x, Dd, Dd);
    // 6) rmsnorm2
    rmsnorm_kernel<<<Tt, 256>>>(x2, r2w, xn2);
    // 7) router + expert grouping
    router_kernel<<<Tt, 256>>>(xn2, wr, br);
    build_lists_kernel<<<1, 256>>>();
    // 8) sparse MoE: gate, up (gathered), silu*mul, down
    moe_gemm_kernel<true><<<dim3(HIDh / BN, Tt / BM, Ee), 256>>>(xn2, wg, gb, HIDh, Dd);
    moe_gemm_kernel<true><<<dim3(HIDh / BN, Tt / BM, Ee), 256>>>(xn2, wu, ub, HIDh, Dd);
    silu_kernel<<<((size_t)NPAIR * HIDh / 4) / 256, 256>>>();
    moe_gemm_kernel<false><<<dim3(Dd / BN, Tt / BM, Ee), 256>>>(gb, wd, eo, Dd, HIDh);
    // 9) combine
    combine_kernel<<<Tt, 256>>>(out);
}

// round 4
// speedup vs baseline: 1.0020x; 1.0020x over previous
#include <cuda_runtime.h>
#include <math.h>

// ---------------- problem constants ----------------
#define Bb   2
#define Ss   1024
#define Dd   2048
#define Hh   16
#define DHh  128
#define Ee   8
#define HIDh 4096
#define Tt   (Bb * Ss)       // 2048 tokens
#define NPAIR (Tt * 2)       // 4096 (token, expert) pairs, always exactly this

// ---------------- device scratch (no allocations allowed) ----------------
__device__ float g_xn1[Tt * Dd];
__device__ float g_q  [Tt * Dd];
__device__ float g_k  [Tt * Dd];
__device__ float g_v  [Tt * Dd];
__device__ float g_att[Tt * Dd];
__device__ float g_x2 [Tt * Dd];
__device__ float g_xn2[Tt * Dd];
__device__ int   g_tid2[NPAIR];     // per (token,k) expert id
__device__ float g_twt [NPAIR];     // per (token,k) routing weight
__device__ int   g_cnt[Ee];
__device__ int   g_off[Ee];
__device__ int   g_tok[NPAIR];      // expert-grouped token ids
__device__ int   g_prow[NPAIR];     // (token,k) -> row in grouped buffers
__device__ float g_gb[(size_t)NPAIR * HIDh];   // gate -> h (in place)
__device__ float g_ub[(size_t)NPAIR * HIDh];   // up
__device__ float g_eo[(size_t)NPAIR * Dd];     // expert outputs

// ---------------- rmsnorm ----------------
__global__ void rmsnorm_kernel(const float* __restrict__ x,
                               const float* __restrict__ w,
                               float* __restrict__ out) {
    int t = blockIdx.x;
    const float* xr = x + (size_t)t * Dd;
    float ss = 0.f;
    for (int i = threadIdx.x; i < Dd; i += 256) { float vv = xr[i]; ss += vv * vv; }
    __shared__ float red[8];
    #pragma unroll
    for (int o = 16; o; o >>= 1) ss += __shfl_xor_sync(0xffffffffu, ss, o);
    if ((threadIdx.x & 31) == 0) red[threadIdx.x >> 5] = ss;
    __syncthreads();
    if (threadIdx.x < 8) {
        float v = red[threadIdx.x];
        #pragma unroll
        for (int o = 4; o; o >>= 1) v += __shfl_xor_sync(0xffu, v, o);
        if (threadIdx.x == 0) red[0] = v;
    }
    __syncthreads();
    float inv = 1.f / sqrtf(red[0] / (float)Dd + 1e-8f);
    float* orow = out + (size_t)t * Dd;
    for (int i = threadIdx.x; i < Dd; i += 256) orow[i] = xr[i] * inv * w[i];
}

// ---------------- generic sgemm: C[M,N] = A[M,K] @ B[N,K]^T (+bias)(+resid) ----------------
#define BM 128
#define BN 128
#define BK 8

__global__ __launch_bounds__(256, 2)
void sgemm_kernel(const float* __restrict__ A, const float* __restrict__ B,
                  float* __restrict__ C, const float* __restrict__ bias,
                  const float* __restrict__ resid, int N, int K) {
    __shared__ float As[BK][BM];
    __shared__ float Bs[BK][BN];
    const int tid = threadIdx.x;
    const int bm = blockIdx.y * BM;
    const int bn = blockIdx.x * BN;
    const int ty = tid >> 4;          // 0..15
    const int tx = tid & 15;          // 0..15
    const int lr = tid >> 1;          // 0..127
    const int lc = (tid & 1) * 4;     // 0 or 4

    const float* Ap = A + (size_t)(bm + lr) * K + lc;
    const float* Bp = B + (size_t)(bn + lr) * K + lc;

    float acc[8][8];
    #pragma unroll
    for (int i = 0; i < 8; i++)
        #pragma unroll
        for (int j = 0; j < 8; j++) acc[i][j] = 0.f;

    for (int k0 = 0; k0 < K; k0 += BK) {
        float4 a4 = *reinterpret_cast<const float4*>(Ap + k0);
        float4 b4 = *reinterpret_cast<const float4*>(Bp + k0);
        As[lc + 0][lr] = a4.x; As[lc + 1][lr] = a4.y; As[lc + 2][lr] = a4.z; As[lc + 3][lr] = a4.w;
        Bs[lc + 0][lr] = b4.x; Bs[lc + 1][lr] = b4.y; Bs[lc + 2][lr] = b4.z; Bs[lc + 3][lr] = b4.w;
        __syncthreads();
        #pragma unroll
        for (int k = 0; k < BK; k++) {
            float ra[8], rb[8];
            *(float4*)(ra)     = *(const float4*)&As[k][ty * 8];
            *(float4*)(ra + 4) = *(const float4*)&As[k][ty * 8 + 4];
            *(float4*)(rb)     = *(const float4*)&Bs[k][tx * 8];
            *(float4*)(rb + 4) = *(const float4*)&Bs[k][tx * 8 + 4];
            #pragma unroll
            for (int i = 0; i < 8; i++)
                #pragma unroll
                for (int j = 0; j < 8; j++)
                    acc[i][j] = fmaf(ra[i], rb[j], acc[i][j]);
        }
        __syncthreads();
    }
    #pragma unroll
    for (int i = 0; i < 8; i++) {
        int row = bm + ty * 8 + i;
        float* crow = C + (size_t)row * N + bn + tx * 8;
        #pragma unroll
        for (int j = 0; j < 8; j += 4) {
            float4 v;
            v.x = acc[i][j + 0]; v.y = acc[i][j + 1]; v.z = acc[i][j + 2]; v.w = acc[i][j + 3];
            if (bias) {
                int c = bn + tx * 8 + j;
                v.x += bias[c]; v.y += bias[c + 1]; v.z += bias[c + 2]; v.w += bias[c + 3];
            }
            if (resid) {
                float4 r = *(const float4*)(resid + (size_t)row * N + bn + tx * 8 + j);
                v.x += r.x; v.y += r.y; v.z += r.z; v.w += r.w;
            }
            *(float4*)(crow + j) = v;
        }
    }
}

// ---------------- MoE grouped gemm (per-expert segments, optional A gather) ----------------
template <bool GATHER>
__global__ __launch_bounds__(256, 2)
void moe_gemm_kernel(const float* __restrict__ Abase, const float* __restrict__ Bbase,
                     float* __restrict__ Cbase, int N, int K) {
    int e = blockIdx.z;
    int cnt = g_cnt[e];
    int bm = blockIdx.y * BM;
    if (bm >= cnt) return;
    int seg = g_off[e];
    int bn = blockIdx.x * BN;

    __shared__ float As[BK][BM];
    __shared__ float Bs[BK][BN];
    const int tid = threadIdx.x;
    const int ty = tid >> 4;
    const int tx = tid & 15;
    const int lr = tid >> 1;
    const int lc = (tid & 1) * 4;

    int gr = bm + lr;
    if (gr >= cnt) gr = cnt - 1;  // clamp (compute garbage, never stored)
    const float* Ap;
    if (GATHER) Ap = Abase + (size_t)g_tok[seg + gr] * K + lc;
    else        Ap = Abase + (size_t)(seg + gr) * K + lc;
    const float* Bp = Bbase + (size_t)e * N * K + (size_t)(bn + lr) * K + lc;

    float acc[8][8];
    #pragma unroll
    for (int i = 0; i < 8; i++)
        #pragma unroll
        for (int j = 0; j < 8; j++) acc[i][j] = 0.f;

    for (int k0 = 0; k0 < K; k0 += BK) {
        float4 a4 = *reinterpret_cast<const float4*>(Ap + k0);
        float4 b4 = *reinterpret_cast<const float4*>(Bp + k0);
        As[lc + 0][lr] = a4.x; As[lc + 1][lr] = a4.y; As[lc + 2][lr] = a4.z; As[lc + 3][lr] = a4.w;
        Bs[lc + 0][lr] = b4.x; Bs[lc + 1][lr] = b4.y; Bs[lc + 2][lr] = b4.z; Bs[lc + 3][lr] = b4.w;
        __syncthreads();
        #pragma unroll
        for (int k = 0; k < BK; k++) {
            float ra[8], rb[8];
            *(float4*)(ra)     = *(const float4*)&As[k][ty * 8];
            *(float4*)(ra + 4) = *(const float4*)&As[k][ty * 8 + 4];
            *(float4*)(rb)     = *(const float4*)&Bs[k][tx * 8];
            *(float4*)(rb + 4) = *(const float4*)&Bs[k][tx * 8 + 4];
            #pragma unroll
            for (int i = 0; i < 8; i++)
                #pragma unroll
                for (int j = 0; j < 8; j++)
                    acc[i][j] = fmaf(ra[i], rb[j], acc[i][j]);
        }
        __syncthreads();
    }
    #pragma unroll
    for (int i = 0; i < 8; i++) {
        int lrow = bm + ty * 8 + i;
        if (lrow >= cnt) continue;
        float* crow = Cbase + (size_t)(seg + lrow) * N + bn + tx * 8;
        #pragma unroll
        for (int j = 0; j < 8; j += 4) {
            float4 v;
            v.x = acc[i][j + 0]; v.y = acc[i][j + 1]; v.z = acc[i][j + 2]; v.w = acc[i][j + 3];
            *(float4*)(crow + j) = v;
        }
    }
}

// ---------------- RoPE (angle depends on HEAD index, per reference) ----------------
__global__ void rope_kernel(float* __restrict__ q) {
    int gid = blockIdx.x * 256 + threadIdx.x;   // over T * H * 64 pairs
    int t = gid >> 10;
    int r = gid & 1023;
    int h = r >> 6;
    int p = r & 63;
    // inv_freq = 10000^(-p/64); angle = h * inv_freq
    float ang = (float)h * expf(-(float)p * (9.210340371976184f / 64.f));
    float c = cosf(ang), s = sinf(ang);
    float* base = q + (size_t)t * Dd + h * DHh + 2 * p;
    float x1 = base[0], x2 = base[1];
    base[0] = x1 * c - x2 * s;
    base[1] = x1 * s + x2 * c;
}

// ---------------- flash-style causal attention ----------------
#define KT 32
__global__ void attn_kernel(const float* __restrict__ Q, const float* __restrict__ Kx,
                            const float* __restrict__ V, float* __restrict__ O) {
    __shared__ float Ks[KT][DHh];
    __shared__ float Vs[KT][DHh];
    int b = blockIdx.z, h = blockIdx.y, qg = blockIdx.x;
    int warp = threadIdx.x >> 5, lane = threadIdx.x & 31;
    int sq = qg * 8 + warp;
    int tq = b * Ss + sq;
    const float* qrow = Q + (size_t)tq * Dd + h * DHh;
    float qr[4];
    #pragma unroll
    for (int i = 0; i < 4; i++) qr[i] = qrow[lane + 32 * i];
    float m = -INFINITY, l = 0.f, o[4] = {0.f, 0.f, 0.f, 0.f};

    int ntiles = (qg * 8 + 8 + KT - 1) / KT;
    for (int kt = 0; kt < ntiles; kt++) {
        for (int idx = threadIdx.x; idx < KT * DHh; idx += 256) {
            int rr = idx >> 7, cc = idx & 127;
            size_t g = ((size_t)(b * Ss + kt * KT + rr)) * Dd + h * DHh + cc;
            Ks[rr][cc] = Kx[g];
            Vs[rr][cc] = V[g];
        }
        __syncthreads();
        int kmax = sq - kt * KT + 1;
        if (kmax > KT) kmax = KT;
        for (int j = 0; j < kmax; j++) {
            float p = qr[0] * Ks[j][lane] + qr[1] * Ks[j][lane + 32] +
                      qr[2] * Ks[j][lane + 64] + qr[3] * Ks[j][lane + 96];
            #pragma unroll
            for (int ofs = 16; ofs; ofs >>= 1) p += __shfl_xor_sync(0xffffffffu, p, ofs);
            p *= 0.08838834764831845f;  // 1/sqrt(128)
            float mnew = fmaxf(m, p);
            float corr = __expf(m - mnew);
            float w = __expf(p - mnew);
            l = l * corr + w;
            #pragma unroll
            for (int i = 0; i < 4; i++) o[i] = o[i] * corr + w * Vs[j][lane + 32 * i];
            m = mnew;
        }
        __syncthreads();
    }
    float invl = 1.f / l;
    float* orow = O + (size_t)tq * Dd + h * DHh;
    #pragma unroll
    for (int i = 0; i < 4; i++) orow[lane + 32 * i] = o[i] * invl;
}

// ---------------- router: logits, top-2, softmax weights ----------------
__global__ void router_kernel(const float* __restrict__ xn, const float* __restrict__ wr,
                              const float* __restrict__ br) {
    int t = blockIdx.x;
    int warp = threadIdx.x >> 5, lane = threadIdx.x & 31;
    const float* xr = xn + (size_t)t * Dd;
    const float* w = wr + (size_t)warp * Dd;
    float s = 0.f;
    for (int i = lane; i < Dd; i += 32) s += xr[i] * w[i];
    #pragma unroll
    for (int o = 16; o; o >>= 1) s += __shfl_xor_sync(0xffffffffu, s, o);
    __shared__ float lg[Ee];
    if (lane == 0) lg[warp] = s + br[warp];
    __syncthreads();
    if (threadIdx.x == 0) {
        int i0 = 0; float v0 = lg[0];
        for (int e = 1; e < Ee; e++) if (lg[e] > v0) { v0 = lg[e]; i0 = e; }
        int i1 = -1; float v1 = -INFINITY;
        for (int e = 0; e < Ee; e++) if (e != i0 && lg[e] > v1) { v1 = lg[e]; i1 = e; }
        float e1 = expf(v1 - v0);
        float w0 = 1.f / (1.f + e1);
        g_tid2[t * 2] = i0; g_tid2[t * 2 + 1] = i1;
        g_twt[t * 2] = w0;  g_twt[t * 2 + 1] = e1 * w0;
    }
}

// ---------------- single-block expert grouping ----------------
__global__ void build_lists_kernel() {
    __shared__ int cnt[Ee], run[Ee];
    int tid = threadIdx.x;
    if (tid < Ee) cnt[tid] = 0;
    __syncthreads();
    for (int i = tid; i < NPAIR; i += 256) atomicAdd(&cnt[g_tid2[i]], 1);
    __syncthreads();
    if (tid == 0) {
        int acc = 0;
        for (int e = 0; e < Ee; e++) { g_cnt[e] = cnt[e]; g_off[e] = acc; run[e] = acc; acc += cnt[e]; }
    }
    __syncthreads();
    for (int i = tid; i < NPAIR; i += 256) {
        int e = g_tid2[i];
        int pos = atomicAdd(&run[e], 1);
        g_tok[pos] = i >> 1;
        g_prow[i] = pos;
    }
}

// ---------------- h = silu(g) * u (in place into g_gb) ----------------
__global__ void silu_kernel() {
    size_t i = ((size_t)blockIdx.x * 256 + threadIdx.x) * 4;
    float4 g = *(float4*)(g_gb + i);
    float4 u = *(float4*)(g_ub + i);
    g.x = g.x / (1.f + expf(-g.x)) * u.x;
    g.y = g.y / (1.f + expf(-g.y)) * u.y;
    g.z = g.z / (1.f + expf(-g.z)) * u.z;
    g.w = g.w / (1.f + expf(-g.w)) * u.w;
    *(float4*)(g_gb + i) = g;
}

// ---------------- final combine: out = x2 + w0*eo0 + w1*eo1 ----------------
__global__ void combine_kernel(float* __restrict__ out) {
    int t = blockIdx.x;
    int r0 = g_prow[t * 2], r1 = g_prow[t * 2 + 1];
    float w0 = g_twt[t * 2], w1 = g_twt[t * 2 + 1];
    const float* e0 = g_eo + (size_t)r0 * Dd;
    const float* e1 = g_eo + (size_t)r1 * Dd;
    const float* xr = g_x2 + (size_t)t * Dd;
    float* orow = out + (size_t)t * Dd;
    for (int i = threadIdx.x; i < Dd; i += 256)
        orow[i] = xr[i] + w0 * e0[i] + w1 * e1[i];
}

// ---------------- host launcher ----------------
extern "C" void kernel_launch(void* const* d_in, const int* in_sizes, int n_in,
                              void* d_out, int out_size) {
    const float* x   = (const float*)d_in[0];
    const float* wq  = (const float*)d_in[1];
    const float* bq  = (const float*)d_in[2];
    const float* wk  = (const float*)d_in[3];
    const float* bk  = (const float*)d_in[4];
    const float* wv  = (const float*)d_in[5];
    const float* bv  = (const float*)d_in[6];
    const float* wo  = (const float*)d_in[7];
    const float* bo  = (const float*)d_in[8];
    const float* wr  = (const float*)d_in[9];
    const float* br  = (const float*)d_in[10];
    const float* wg  = (const float*)d_in[11];
    const float* wu  = (const float*)d_in[12];
    const float* wd  = (const float*)d_in[13];
    const float* r1w = (const float*)d_in[14];
    const float* r2w = (const float*)d_in[15];
    float* out = (float*)d_out;

    float *xn1, *q, *k, *v, *att, *x2, *xn2, *gb, *ub, *eo;
    cudaGetSymbolAddress((void**)&xn1, g_xn1);
    cudaGetSymbolAddress((void**)&q,   g_q);
    cudaGetSymbolAddress((void**)&k,   g_k);
    cudaGetSymbolAddress((void**)&v,   g_v);
    cudaGetSymbolAddress((void**)&att, g_att);
    cudaGetSymbolAddress((void**)&x2,  g_x2);
    cudaGetSymbolAddress((void**)&xn2, g_xn2);
    cudaGetSymbolAddress((void**)&gb,  g_gb);
    cudaGetSymbolAddress((void**)&ub,  g_ub);
    cudaGetSymbolAddress((void**)&eo,  g_eo);

    // 1) rmsnorm1
    rmsnorm_kernel<<<Tt, 256>>>(x, r1w, xn1);
    // 2) QKV projections
    sgemm_kernel<<<dim3(Dd / BN, Tt / BM), 256>>>(xn1, wq, q, bq, nullptr, Dd, Dd);
    sgemm_kernel<<<dim3(Dd / BN, Tt / BM), 256>>>(xn1, wk, k, bk, nullptr, Dd, Dd);
    sgemm_kernel<<<dim3(Dd / BN, Tt / BM), 256>>>(xn1, wv, v, bv, nullptr, Dd, Dd);
    // 3) RoPE on q, k
    rope_kernel<<<(Tt * Hh * 64) / 256, 256>>>(q);
    rope_kernel<<<(Tt * Hh * 64) / 256, 256>>>(k);
    // 4) causal attention
    attn_kernel<<<dim3(Ss / 8, Hh, Bb), 256>>>(q, k, v, att);
    // 5) output projection + residual
    sgemm_kernel<<<dim3(Dd / BN, Tt / BM), 256>>>(att, wo, x2, bo, x, Dd, Dd);
    // 6) rmsnorm2
    rmsnorm_kernel<<<Tt, 256>>>(x2, r2w, xn2);
    // 7) router + expert grouping
    router_kernel<<<Tt, 256>>>(xn2, wr, br);
    build_lists_kernel<<<1, 256>>>();
    // 8) sparse MoE: gate, up (gathered), silu*mul, down
    moe_gemm_kernel<true><<<dim3(HIDh / BN, Tt / BM, Ee), 256>>>(xn2, wg, gb, HIDh, Dd);
    moe_gemm_kernel<true><<<dim3(HIDh / BN, Tt / BM, Ee), 256>>>(xn2, wu, ub, HIDh, Dd);
    silu_kernel<<<((size_t)NPAIR * HIDh / 4) / 256, 256>>>();
    moe_gemm_kernel<false><<<dim3(Dd / BN, Tt / BM, Ee), 256>>>(gb, wd, eo, Dd, HIDh);
    // 9) combine
    combine_kernel<<<Tt, 256>>>(out);
}